// round 4
// baseline (speedup 1.0000x reference)
#include <cuda_runtime.h>
#include <math.h>

#define EMB 1024
#define SEQ 1024
#define NB 8
#define HEADS 16
#define HD 64
#define ROWS (NB * SEQ)          // 8192
#define OUT_ELEMS ((size_t)ROWS * EMB)   // 8388608

// Scratch (static device globals; no runtime allocation allowed)
__device__ float g_Q[ROWS * EMB];
__device__ float g_K[ROWS * EMB];
__device__ float g_V[ROWS * EMB];
__device__ float g_O[ROWS * EMB];

// ---------------------------------------------------------------------------
// Generic C[M,1024] = A[M,1024] @ B[1024,1024]^T (+bias), 128x128x8 tiles.
// Both A and B are row-major with K contiguous (nn.Linear: x @ W^T).
// grid = (N/128, M/128), block = 256
// ---------------------------------------------------------------------------
__global__ __launch_bounds__(256) void sgemm_nt_bias(
    const float* __restrict__ A, const float* __restrict__ B,
    float* __restrict__ C, const float* __restrict__ bias)
{
    __shared__ float As[8][132];
    __shared__ float Bs[8][132];
    const int tid = threadIdx.x;
    const int m0 = blockIdx.y * 128;
    const int n0 = blockIdx.x * 128;
    const int lr = tid >> 1;            // 0..127
    const int lc = (tid & 1) * 4;       // 0 or 4
    const int tr = (tid >> 4) * 8;
    const int tc = (tid & 15) * 8;

    float acc[8][8] = {};
    const float* Ap = A + (size_t)(m0 + lr) * EMB + lc;
    const float* Bp = B + (size_t)(n0 + lr) * EMB + lc;

    for (int k0 = 0; k0 < EMB; k0 += 8) {
        float4 a4 = *(const float4*)(Ap + k0);
        float4 b4 = *(const float4*)(Bp + k0);
        As[lc + 0][lr] = a4.x; As[lc + 1][lr] = a4.y;
        As[lc + 2][lr] = a4.z; As[lc + 3][lr] = a4.w;
        Bs[lc + 0][lr] = b4.x; Bs[lc + 1][lr] = b4.y;
        Bs[lc + 2][lr] = b4.z; Bs[lc + 3][lr] = b4.w;
        __syncthreads();
#pragma unroll
        for (int kk = 0; kk < 8; kk++) {
            float4 ra0 = *(const float4*)&As[kk][tr];
            float4 ra1 = *(const float4*)&As[kk][tr + 4];
            float4 rb0 = *(const float4*)&Bs[kk][tc];
            float4 rb1 = *(const float4*)&Bs[kk][tc + 4];
            float ra[8] = {ra0.x, ra0.y, ra0.z, ra0.w, ra1.x, ra1.y, ra1.z, ra1.w};
            float rb[8] = {rb0.x, rb0.y, rb0.z, rb0.w, rb1.x, rb1.y, rb1.z, rb1.w};
#pragma unroll
            for (int i = 0; i < 8; i++)
#pragma unroll
                for (int j = 0; j < 8; j++)
                    acc[i][j] = fmaf(ra[i], rb[j], acc[i][j]);
        }
        __syncthreads();
    }

#pragma unroll
    for (int i = 0; i < 8; i++) {
#pragma unroll
        for (int j = 0; j < 8; j++) {
            float v = acc[i][j];
            if (bias) v += bias[n0 + tc + j];
            C[(size_t)(m0 + tr + i) * EMB + n0 + tc + j] = v;
        }
    }
}

// ---------------------------------------------------------------------------
// energy[n,h,q,k] = (1/8) * sum_d q[n,q,h,d] * k[n,k,h,d]
// Per (n,h): C[1024,1024] = 0.125 * A[1024,64] @ B[1024,64]^T, lda=ldb=1024
// grid = (8, 8, 128), block = 256
// ---------------------------------------------------------------------------
__global__ __launch_bounds__(256) void energy_kernel(float* __restrict__ att)
{
    const int z = blockIdx.z;         // n*16 + h
    const int n = z >> 4, h = z & 15;
    const float* A = g_Q + (size_t)n * SEQ * EMB + h * HD;
    const float* B = g_K + (size_t)n * SEQ * EMB + h * HD;
    float* C = att + (size_t)z * SEQ * SEQ;

    __shared__ float As[8][132];
    __shared__ float Bs[8][132];
    const int tid = threadIdx.x;
    const int m0 = blockIdx.y * 128;
    const int n0 = blockIdx.x * 128;
    const int lr = tid >> 1;
    const int lc = (tid & 1) * 4;
    const int tr = (tid >> 4) * 8;
    const int tc = (tid & 15) * 8;

    float acc[8][8] = {};
    const float* Ap = A + (size_t)(m0 + lr) * EMB + lc;
    const float* Bp = B + (size_t)(n0 + lr) * EMB + lc;

    for (int k0 = 0; k0 < HD; k0 += 8) {
        float4 a4 = *(const float4*)(Ap + k0);
        float4 b4 = *(const float4*)(Bp + k0);
        As[lc + 0][lr] = a4.x; As[lc + 1][lr] = a4.y;
        As[lc + 2][lr] = a4.z; As[lc + 3][lr] = a4.w;
        Bs[lc + 0][lr] = b4.x; Bs[lc + 1][lr] = b4.y;
        Bs[lc + 2][lr] = b4.z; Bs[lc + 3][lr] = b4.w;
        __syncthreads();
#pragma unroll
        for (int kk = 0; kk < 8; kk++) {
            float4 ra0 = *(const float4*)&As[kk][tr];
            float4 ra1 = *(const float4*)&As[kk][tr + 4];
            float4 rb0 = *(const float4*)&Bs[kk][tc];
            float4 rb1 = *(const float4*)&Bs[kk][tc + 4];
            float ra[8] = {ra0.x, ra0.y, ra0.z, ra0.w, ra1.x, ra1.y, ra1.z, ra1.w};
            float rb[8] = {rb0.x, rb0.y, rb0.z, rb0.w, rb1.x, rb1.y, rb1.z, rb1.w};
#pragma unroll
            for (int i = 0; i < 8; i++)
#pragma unroll
                for (int j = 0; j < 8; j++)
                    acc[i][j] = fmaf(ra[i], rb[j], acc[i][j]);
        }
        __syncthreads();
    }

#pragma unroll
    for (int i = 0; i < 8; i++)
#pragma unroll
        for (int j = 0; j < 8; j++)
            C[(size_t)(m0 + tr + i) * SEQ + n0 + tc + j] = 0.125f * acc[i][j];
}

// ---------------------------------------------------------------------------
// Row softmax over last dim (1024), in place, with mask[n,k] (-1e20 where 0).
// One 256-thread block per row; row index = z*1024 + q, z = n*16 + h.
// ---------------------------------------------------------------------------
__global__ __launch_bounds__(256) void softmax_kernel(
    float* __restrict__ att, const int* __restrict__ mask)
{
    __shared__ float sbuf[8];
    const int row = blockIdx.x;           // 0 .. 131071
    const int n = row >> 14;              // / (16*1024)
    float* p = att + (size_t)row * SEQ;
    const int c = threadIdx.x * 4;
    const int* mrow = mask + n * SEQ;

    float4 x = *(const float4*)(p + c);
    if (mrow[c + 0] == 0) x.x = -1e20f;
    if (mrow[c + 1] == 0) x.y = -1e20f;
    if (mrow[c + 2] == 0) x.z = -1e20f;
    if (mrow[c + 3] == 0) x.w = -1e20f;

    float m = fmaxf(fmaxf(x.x, x.y), fmaxf(x.z, x.w));
#pragma unroll
    for (int o = 16; o; o >>= 1) m = fmaxf(m, __shfl_xor_sync(0xffffffffu, m, o));
    if ((threadIdx.x & 31) == 0) sbuf[threadIdx.x >> 5] = m;
    __syncthreads();
    m = sbuf[0];
#pragma unroll
    for (int i = 1; i < 8; i++) m = fmaxf(m, sbuf[i]);

    float4 e;
    e.x = __expf(x.x - m);
    e.y = __expf(x.y - m);
    e.z = __expf(x.z - m);
    e.w = __expf(x.w - m);
    float s = (e.x + e.y) + (e.z + e.w);
#pragma unroll
    for (int o = 16; o; o >>= 1) s += __shfl_xor_sync(0xffffffffu, s, o);
    __syncthreads();  // sbuf reuse
    if ((threadIdx.x & 31) == 0) sbuf[threadIdx.x >> 5] = s;
    __syncthreads();
    s = 0.f;
#pragma unroll
    for (int i = 0; i < 8; i++) s += sbuf[i];

    const float inv = 1.0f / s;
    e.x *= inv; e.y *= inv; e.z *= inv; e.w *= inv;
    *(float4*)(p + c) = e;
}

// ---------------------------------------------------------------------------
// out_head[n,q,h,d] = sum_a att[n,h,q,a] * v[n,a,h,d]
// Per (n,h): C[1024,64] = A[1024,1024] @ B[1024,64]; ldb=ldc=1024.
// Tiles 128x64x16; grid = (1, 8, 128), block = 256, microtile 8x4.
// ---------------------------------------------------------------------------
__global__ __launch_bounds__(256) void attv_kernel(const float* __restrict__ att)
{
    const int z = blockIdx.z;
    const int n = z >> 4, h = z & 15;
    const float* A = att + (size_t)z * SEQ * SEQ;
    const float* B = g_V + (size_t)n * SEQ * EMB + h * HD;
    float* C = g_O + (size_t)n * SEQ * EMB + h * HD;

    __shared__ float As[16][132];
    __shared__ float Bs[16][68];
    const int tid = threadIdx.x;
    const int m0 = blockIdx.y * 128;
    const int ar = tid >> 2;            // 0..63 (also +64)
    const int ac = (tid & 3) * 4;       // 0,4,8,12
    const int br = tid >> 4;            // 0..15
    const int bc = (tid & 15) * 4;      // 0..60
    const int tr = (tid >> 4) * 8;
    const int tc = (tid & 15) * 4;

    float acc[8][4] = {};

    for (int k0 = 0; k0 < SEQ; k0 += 16) {
        float4 a0 = *(const float4*)(A + (size_t)(m0 + ar) * SEQ + k0 + ac);
        float4 a1 = *(const float4*)(A + (size_t)(m0 + ar + 64) * SEQ + k0 + ac);
        float4 b4 = *(const float4*)(B + (size_t)(k0 + br) * EMB + bc);
        As[ac + 0][ar] = a0.x; As[ac + 1][ar] = a0.y;
        As[ac + 2][ar] = a0.z; As[ac + 3][ar] = a0.w;
        As[ac + 0][ar + 64] = a1.x; As[ac + 1][ar + 64] = a1.y;
        As[ac + 2][ar + 64] = a1.z; As[ac + 3][ar + 64] = a1.w;
        *(float4*)&Bs[br][bc] = b4;
        __syncthreads();
#pragma unroll
        for (int kk = 0; kk < 16; kk++) {
            float4 ra0 = *(const float4*)&As[kk][tr];
            float4 ra1 = *(const float4*)&As[kk][tr + 4];
            float4 rb = *(const float4*)&Bs[kk][tc];
            float ra[8] = {ra0.x, ra0.y, ra0.z, ra0.w, ra1.x, ra1.y, ra1.z, ra1.w};
            float rbv[4] = {rb.x, rb.y, rb.z, rb.w};
#pragma unroll
            for (int i = 0; i < 8; i++)
#pragma unroll
                for (int j = 0; j < 4; j++)
                    acc[i][j] = fmaf(ra[i], rbv[j], acc[i][j]);
        }
        __syncthreads();
    }

#pragma unroll
    for (int i = 0; i < 8; i++)
#pragma unroll
        for (int j = 0; j < 4; j++)
            C[(size_t)(m0 + tr + i) * EMB + tc + j] = acc[i][j];
}

// ---------------------------------------------------------------------------
extern "C" void kernel_launch(void* const* d_in, const int* in_sizes, int n_in,
                              void* d_out, int out_size)
{
    const float* value = (const float*)d_in[0];
    const float* key_  = (const float*)d_in[1];
    const float* query = (const float*)d_in[2];
    const int*   mask  = (const int*)d_in[3];
    const float* Wv    = (const float*)d_in[4];
    const float* Wk    = (const float*)d_in[5];
    const float* Wq    = (const float*)d_in[6];
    const float* Wo    = (const float*)d_in[7];
    const float* bo    = (const float*)d_in[8];

    float* out = (float*)d_out;                 // [8,1024,1024]
    float* att = out + OUT_ELEMS;               // [8,16,1024,1024]

    float *qp, *kp, *vp, *op;
    cudaGetSymbolAddress((void**)&qp, g_Q);
    cudaGetSymbolAddress((void**)&kp, g_K);
    cudaGetSymbolAddress((void**)&vp, g_V);
    cudaGetSymbolAddress((void**)&op, g_O);

    dim3 blk(256);
    dim3 gproj(EMB / 128, ROWS / 128);          // (8, 64)

    sgemm_nt_bias<<<gproj, blk>>>(query, Wq, qp, nullptr);
    sgemm_nt_bias<<<gproj, blk>>>(key_,  Wk, kp, nullptr);
    sgemm_nt_bias<<<gproj, blk>>>(value, Wv, vp, nullptr);

    energy_kernel<<<dim3(8, 8, NB * HEADS), blk>>>(att);
    softmax_kernel<<<NB * HEADS * SEQ, 256>>>(att, mask);
    attv_kernel<<<dim3(1, 8, NB * HEADS), blk>>>(att);

    sgemm_nt_bias<<<gproj, blk>>>(op, Wo, out, bo);
}

// round 5
// speedup vs baseline: 1.8459x; 1.8459x over previous
#include <cuda_runtime.h>
#include <math.h>

#define EMB 1024
#define SEQ 1024
#define NB 8
#define HEADS 16
#define HD 64
#define ROWS (NB * SEQ)                  // 8192
#define OUT_ELEMS ((size_t)ROWS * EMB)   // 8388608

#define BM 128
#define BN 128
#define BK 32

// Scratch (static device globals; no runtime allocation allowed)
__device__ float g_Q[ROWS * EMB];
__device__ float g_K[ROWS * EMB];
__device__ float g_V[ROWS * EMB];
__device__ float g_O[ROWS * EMB];

// ---------------------------------------------------------------------------
// TF32 helpers
// ---------------------------------------------------------------------------
__device__ __forceinline__ unsigned f2tf(float x) {
    unsigned r;
    asm("cvt.rna.tf32.f32 %0, %1;" : "=r"(r) : "f"(x));
    return r;
}

__device__ __forceinline__ void mma_tf32(float* c, const unsigned* a, const unsigned* b) {
    asm volatile(
        "mma.sync.aligned.m16n8k8.row.col.f32.tf32.tf32.f32 "
        "{%0,%1,%2,%3},{%4,%5,%6,%7},{%8,%9},{%0,%1,%2,%3};\n"
        : "+f"(c[0]), "+f"(c[1]), "+f"(c[2]), "+f"(c[3])
        : "r"(a[0]), "r"(a[1]), "r"(a[2]), "r"(a[3]),
          "r"(b[0]), "r"(b[1]));
}

// ---------------------------------------------------------------------------
// NT GEMM core: C[.,.] = alpha * A(row-major, lda) @ B(row-major, ldb)^T + bias
// CTA tile 128x128xK, BK=32, 256 threads, warp tile 32x64, mma m16n8k8 tf32.
// smem layout k-major: As[k][m] / Bs[k][n], stride 132 words (conflict-free).
// ---------------------------------------------------------------------------
template <int KDIM>
__device__ __forceinline__ void gemm_nt_body(
    const float* __restrict__ A, int lda,
    const float* __restrict__ B, int ldb,
    float* __restrict__ C, int ldc,
    float alpha, const float* __restrict__ bias)
{
    __shared__ unsigned As[BK][132];
    __shared__ unsigned Bs[BK][132];

    const int tid = threadIdx.x;
    const int m0 = blockIdx.y * BM;
    const int n0 = blockIdx.x * BN;

    // staging loader: each thread handles one row, 16 consecutive k columns
    const int lrow = tid >> 1;
    const int lcol = (tid & 1) * 16;

    const int w    = tid >> 5;
    const int wr   = (w >> 1) * 32;   // warp m offset within CTA tile
    const int wc   = (w & 1) * 64;    // warp n offset
    const int lane = tid & 31;
    const int g    = lane >> 2;       // group id 0..7
    const int t    = lane & 3;        // thread-in-group 0..3

    float acc[2][8][4];
#pragma unroll
    for (int i = 0; i < 2; i++)
#pragma unroll
        for (int j = 0; j < 8; j++)
#pragma unroll
            for (int k = 0; k < 4; k++) acc[i][j][k] = 0.f;

    const float* Ap = A + (size_t)(m0 + lrow) * lda + lcol;
    const float* Bp = B + (size_t)(n0 + lrow) * ldb + lcol;

    float4 av[4], bv[4];
#pragma unroll
    for (int i = 0; i < 4; i++) {
        av[i] = *(const float4*)(Ap + i * 4);
        bv[i] = *(const float4*)(Bp + i * 4);
    }

#pragma unroll 1
    for (int kt = 0; kt < KDIM / BK; kt++) {
        // stage registers -> smem (transposed, tf32-converted)
#pragma unroll
        for (int i = 0; i < 4; i++) {
            As[lcol + i * 4 + 0][lrow] = f2tf(av[i].x);
            As[lcol + i * 4 + 1][lrow] = f2tf(av[i].y);
            As[lcol + i * 4 + 2][lrow] = f2tf(av[i].z);
            As[lcol + i * 4 + 3][lrow] = f2tf(av[i].w);
            Bs[lcol + i * 4 + 0][lrow] = f2tf(bv[i].x);
            Bs[lcol + i * 4 + 1][lrow] = f2tf(bv[i].y);
            Bs[lcol + i * 4 + 2][lrow] = f2tf(bv[i].z);
            Bs[lcol + i * 4 + 3][lrow] = f2tf(bv[i].w);
        }
        __syncthreads();

        // prefetch next global tile while computing this one
        if (kt + 1 < KDIM / BK) {
#pragma unroll
            for (int i = 0; i < 4; i++) {
                av[i] = *(const float4*)(Ap + (kt + 1) * BK + i * 4);
                bv[i] = *(const float4*)(Bp + (kt + 1) * BK + i * 4);
            }
        }

#pragma unroll
        for (int kk = 0; kk < BK; kk += 8) {
            unsigned af[2][4], bf[8][2];
#pragma unroll
            for (int mi = 0; mi < 2; mi++) {
                af[mi][0] = As[kk + t    ][wr + mi * 16 + g    ];
                af[mi][1] = As[kk + t    ][wr + mi * 16 + g + 8];
                af[mi][2] = As[kk + t + 4][wr + mi * 16 + g    ];
                af[mi][3] = As[kk + t + 4][wr + mi * 16 + g + 8];
            }
#pragma unroll
            for (int ni = 0; ni < 8; ni++) {
                bf[ni][0] = Bs[kk + t    ][wc + ni * 8 + g];
                bf[ni][1] = Bs[kk + t + 4][wc + ni * 8 + g];
            }
#pragma unroll
            for (int mi = 0; mi < 2; mi++)
#pragma unroll
                for (int ni = 0; ni < 8; ni++)
                    mma_tf32(acc[mi][ni], af[mi], bf[ni]);
        }
        __syncthreads();
    }

    // epilogue
#pragma unroll
    for (int mi = 0; mi < 2; mi++) {
#pragma unroll
        for (int ni = 0; ni < 8; ni++) {
            const int row = m0 + wr + mi * 16 + g;
            const int col = n0 + wc + ni * 8 + t * 2;
            float b0 = 0.f, b1 = 0.f;
            if (bias) { b0 = bias[col]; b1 = bias[col + 1]; }
            *(float2*)&C[(size_t)row * ldc + col] =
                make_float2(acc[mi][ni][0] * alpha + b0, acc[mi][ni][1] * alpha + b1);
            *(float2*)&C[(size_t)(row + 8) * ldc + col] =
                make_float2(acc[mi][ni][2] * alpha + b0, acc[mi][ni][3] * alpha + b1);
        }
    }
}

// C[8192,1024] = A[8192,1024] @ W[1024,1024]^T (+bias)
__global__ __launch_bounds__(256, 1) void proj_tf32(
    const float* __restrict__ A, const float* __restrict__ B,
    float* __restrict__ C, const float* __restrict__ bias)
{
    gemm_nt_body<EMB>(A, EMB, B, EMB, C, EMB, 1.0f, bias);
}

// att[z,q,k] = 0.125 * Q[n,q,h,:] . K[n,k,h,:]  (z = n*16+h), K-dim = 64
__global__ __launch_bounds__(256, 1) void energy_tf32(float* __restrict__ att)
{
    const int z = blockIdx.z;
    const int n = z >> 4, h = z & 15;
    gemm_nt_body<HD>(g_Q + (size_t)n * SEQ * EMB + h * HD, EMB,
                     g_K + (size_t)n * SEQ * EMB + h * HD, EMB,
                     att + (size_t)z * SEQ * SEQ, SEQ, 0.125f, nullptr);
}

// ---------------------------------------------------------------------------
// Row softmax over last dim (1024), in place, with mask[n,k] (-1e20 where 0).
// ---------------------------------------------------------------------------
__global__ __launch_bounds__(256) void softmax_kernel(
    float* __restrict__ att, const int* __restrict__ mask)
{
    __shared__ float sbuf[8];
    const int row = blockIdx.x;
    const int n = row >> 14;
    float* p = att + (size_t)row * SEQ;
    const int c = threadIdx.x * 4;
    const int* mrow = mask + n * SEQ;

    float4 x = *(const float4*)(p + c);
    if (mrow[c + 0] == 0) x.x = -1e20f;
    if (mrow[c + 1] == 0) x.y = -1e20f;
    if (mrow[c + 2] == 0) x.z = -1e20f;
    if (mrow[c + 3] == 0) x.w = -1e20f;

    float m = fmaxf(fmaxf(x.x, x.y), fmaxf(x.z, x.w));
#pragma unroll
    for (int o = 16; o; o >>= 1) m = fmaxf(m, __shfl_xor_sync(0xffffffffu, m, o));
    if ((threadIdx.x & 31) == 0) sbuf[threadIdx.x >> 5] = m;
    __syncthreads();
    m = sbuf[0];
#pragma unroll
    for (int i = 1; i < 8; i++) m = fmaxf(m, sbuf[i]);

    float4 e;
    e.x = __expf(x.x - m);
    e.y = __expf(x.y - m);
    e.z = __expf(x.z - m);
    e.w = __expf(x.w - m);
    float s = (e.x + e.y) + (e.z + e.w);
#pragma unroll
    for (int o = 16; o; o >>= 1) s += __shfl_xor_sync(0xffffffffu, s, o);
    __syncthreads();
    if ((threadIdx.x & 31) == 0) sbuf[threadIdx.x >> 5] = s;
    __syncthreads();
    s = 0.f;
#pragma unroll
    for (int i = 0; i < 8; i++) s += sbuf[i];

    const float inv = 1.0f / s;
    e.x *= inv; e.y *= inv; e.z *= inv; e.w *= inv;
    *(float4*)(p + c) = e;
}

// ---------------------------------------------------------------------------
// att*V (NN form): per z = n*16+h,  C[1024,64] = P[1024,1024] @ V[1024,64]
// P row-major (ld SEQ), V row-major [k][n] (ld EMB) -> staged directly k-major.
// CTA tile 128x64x32, warp tile 32x32.
// ---------------------------------------------------------------------------
__global__ __launch_bounds__(256, 1) void attv_tf32(const float* __restrict__ att)
{
    const int z = blockIdx.z;
    const int n = z >> 4, h = z & 15;
    const float* A = att + (size_t)z * SEQ * SEQ;
    const float* B = g_V + (size_t)n * SEQ * EMB + h * HD;
    float* C = g_O + (size_t)n * SEQ * EMB + h * HD;

    __shared__ unsigned As[BK][132];
    __shared__ unsigned Bs[BK][72];

    const int tid = threadIdx.x;
    const int m0 = blockIdx.y * BM;

    const int lrow = tid >> 1;
    const int lcol = (tid & 1) * 16;
    const int brow = tid >> 3;          // 0..31 (k)
    const int bcol = (tid & 7) * 8;     // 0..56 (n)

    const int w    = tid >> 5;
    const int wr   = (w >> 1) * 32;
    const int wc   = (w & 1) * 32;
    const int lane = tid & 31;
    const int g    = lane >> 2;
    const int t    = lane & 3;

    float acc[2][4][4];
#pragma unroll
    for (int i = 0; i < 2; i++)
#pragma unroll
        for (int j = 0; j < 4; j++)
#pragma unroll
            for (int k = 0; k < 4; k++) acc[i][j][k] = 0.f;

    const float* Ap = A + (size_t)(m0 + lrow) * SEQ + lcol;
    const float* Bp = B + (size_t)brow * EMB + bcol;

    float4 av[4], bv[2];
#pragma unroll
    for (int i = 0; i < 4; i++) av[i] = *(const float4*)(Ap + i * 4);
    bv[0] = *(const float4*)(Bp);
    bv[1] = *(const float4*)(Bp + 4);

#pragma unroll 1
    for (int kt = 0; kt < SEQ / BK; kt++) {
#pragma unroll
        for (int i = 0; i < 4; i++) {
            As[lcol + i * 4 + 0][lrow] = f2tf(av[i].x);
            As[lcol + i * 4 + 1][lrow] = f2tf(av[i].y);
            As[lcol + i * 4 + 2][lrow] = f2tf(av[i].z);
            As[lcol + i * 4 + 3][lrow] = f2tf(av[i].w);
        }
        Bs[brow][bcol + 0] = f2tf(bv[0].x);
        Bs[brow][bcol + 1] = f2tf(bv[0].y);
        Bs[brow][bcol + 2] = f2tf(bv[0].z);
        Bs[brow][bcol + 3] = f2tf(bv[0].w);
        Bs[brow][bcol + 4] = f2tf(bv[1].x);
        Bs[brow][bcol + 5] = f2tf(bv[1].y);
        Bs[brow][bcol + 6] = f2tf(bv[1].z);
        Bs[brow][bcol + 7] = f2tf(bv[1].w);
        __syncthreads();

        if (kt + 1 < SEQ / BK) {
#pragma unroll
            for (int i = 0; i < 4; i++)
                av[i] = *(const float4*)(Ap + (kt + 1) * BK + i * 4);
            bv[0] = *(const float4*)(Bp + (size_t)(kt + 1) * BK * EMB);
            bv[1] = *(const float4*)(Bp + (size_t)(kt + 1) * BK * EMB + 4);
        }

#pragma unroll
        for (int kk = 0; kk < BK; kk += 8) {
            unsigned af[2][4], bf[4][2];
#pragma unroll
            for (int mi = 0; mi < 2; mi++) {
                af[mi][0] = As[kk + t    ][wr + mi * 16 + g    ];
                af[mi][1] = As[kk + t    ][wr + mi * 16 + g + 8];
                af[mi][2] = As[kk + t + 4][wr + mi * 16 + g    ];
                af[mi][3] = As[kk + t + 4][wr + mi * 16 + g + 8];
            }
#pragma unroll
            for (int ni = 0; ni < 4; ni++) {
                bf[ni][0] = Bs[kk + t    ][wc + ni * 8 + g];
                bf[ni][1] = Bs[kk + t + 4][wc + ni * 8 + g];
            }
#pragma unroll
            for (int mi = 0; mi < 2; mi++)
#pragma unroll
                for (int ni = 0; ni < 4; ni++)
                    mma_tf32(acc[mi][ni], af[mi], bf[ni]);
        }
        __syncthreads();
    }

#pragma unroll
    for (int mi = 0; mi < 2; mi++) {
#pragma unroll
        for (int ni = 0; ni < 4; ni++) {
            const int row = m0 + wr + mi * 16 + g;
            const int col = wc + ni * 8 + t * 2;
            *(float2*)&C[(size_t)row * EMB + col] =
                make_float2(acc[mi][ni][0], acc[mi][ni][1]);
            *(float2*)&C[(size_t)(row + 8) * EMB + col] =
                make_float2(acc[mi][ni][2], acc[mi][ni][3]);
        }
    }
}

// ---------------------------------------------------------------------------
extern "C" void kernel_launch(void* const* d_in, const int* in_sizes, int n_in,
                              void* d_out, int out_size)
{
    const float* value = (const float*)d_in[0];
    const float* key_  = (const float*)d_in[1];
    const float* query = (const float*)d_in[2];
    const int*   mask  = (const int*)d_in[3];
    const float* Wv    = (const float*)d_in[4];
    const float* Wk    = (const float*)d_in[5];
    const float* Wq    = (const float*)d_in[6];
    const float* Wo    = (const float*)d_in[7];
    const float* bo    = (const float*)d_in[8];

    float* out = (float*)d_out;                 // [8,1024,1024]
    float* att = out + OUT_ELEMS;               // [8,16,1024,1024]

    float *qp, *kp, *vp, *op;
    cudaGetSymbolAddress((void**)&qp, g_Q);
    cudaGetSymbolAddress((void**)&kp, g_K);
    cudaGetSymbolAddress((void**)&vp, g_V);
    cudaGetSymbolAddress((void**)&op, g_O);

    dim3 blk(256);
    dim3 gproj(EMB / BN, ROWS / BM);            // (8, 64)

    proj_tf32<<<gproj, blk>>>(query, Wq, qp, nullptr);
    proj_tf32<<<gproj, blk>>>(key_,  Wk, kp, nullptr);
    proj_tf32<<<gproj, blk>>>(value, Wv, vp, nullptr);

    energy_tf32<<<dim3(SEQ / BN, SEQ / BM, NB * HEADS), blk>>>(att);
    softmax_kernel<<<NB * HEADS * SEQ, 256>>>(att, mask);
    attv_tf32<<<dim3(1, SEQ / BM, NB * HEADS), blk>>>(att);

    proj_tf32<<<gproj, blk>>>(op, Wo, out, bo);
}

// round 6
// speedup vs baseline: 2.1228x; 1.1500x over previous
#include <cuda_runtime.h>
#include <math.h>

#define EMB 1024
#define SEQ 1024
#define NB 8
#define HEADS 16
#define HD 64
#define ROWS (NB * SEQ)                  // 8192
#define OUT_ELEMS ((size_t)ROWS * EMB)   // 8388608

// Scratch (static device globals; no runtime allocation allowed)
__device__ float g_Q[ROWS * EMB];
__device__ float g_K[ROWS * EMB];
__device__ float g_V[ROWS * EMB];
__device__ float g_O[ROWS * EMB];

// ---------------------------------------------------------------------------
// TF32 helpers
// ---------------------------------------------------------------------------
__device__ __forceinline__ unsigned f2tf(float x) {
    unsigned r;
    asm("cvt.rna.tf32.f32 %0, %1;" : "=r"(r) : "f"(x));
    return r;
}

__device__ __forceinline__ void mma_tf32(float* c, const unsigned* a, const unsigned* b) {
    asm volatile(
        "mma.sync.aligned.m16n8k8.row.col.f32.tf32.tf32.f32 "
        "{%0,%1,%2,%3},{%4,%5,%6,%7},{%8,%9},{%0,%1,%2,%3};\n"
        : "+f"(c[0]), "+f"(c[1]), "+f"(c[2]), "+f"(c[3])
        : "r"(a[0]), "r"(a[1]), "r"(a[2]), "r"(a[3]),
          "r"(b[0]), "r"(b[1]));
}

// ---------------------------------------------------------------------------
// NT GEMM core: C = alpha * A(row-major,lda) @ B(row-major,ldb)^T + bias
// CTA 128x128, 128 threads (4 warps), warp tile 64x64, BK=16 double-buffered.
// smem k-major [k][mn], stride 136 words:
//   fragment LDS bank = t*8+g  -> conflict-free
//   staging  STS bank = j*8 + lane -> conflict-free
//   staging  LDG: lane = consecutive rows, 32B per lane -> full sectors
// ---------------------------------------------------------------------------
template <int KDIM>
__device__ __forceinline__ void gemm_nt_body(
    const float* __restrict__ A, int lda,
    const float* __restrict__ B, int ldb,
    float* __restrict__ C, int ldc,
    float alpha, const float* __restrict__ bias)
{
    __shared__ unsigned As[2][16][136];
    __shared__ unsigned Bs[2][16][136];

    const int tid  = threadIdx.x;
    const int m0   = blockIdx.y * 128;
    const int n0   = blockIdx.x * 128;
    const int warp = tid >> 5;
    const int lane = tid & 31;
    const int wr   = (warp >> 1) * 64;
    const int wc   = (warp & 1) * 64;
    const int g    = lane >> 2;
    const int t    = lane & 3;

    const int rowA = tid & 63;           // staging row (two groups: +0, +64)
    const int kc   = (tid >> 6) * 8;     // staging k offset (0 or 8)

    float acc[4][8][4] = {};

    const float* Ap = A + (size_t)(m0 + rowA) * lda + kc;
    const float* Bp = B + (size_t)(n0 + rowA) * ldb + kc;

    float4 av[2][2], bv[2][2];           // [row-group][half]

    auto ldtile = [&](int kt) {
#pragma unroll
        for (int r = 0; r < 2; r++)
#pragma unroll
            for (int h = 0; h < 2; h++) {
                av[r][h] = *(const float4*)(Ap + (size_t)r * 64 * lda + kt * 16 + h * 4);
                bv[r][h] = *(const float4*)(Bp + (size_t)r * 64 * ldb + kt * 16 + h * 4);
            }
    };
    auto sttile = [&](int buf) {
#pragma unroll
        for (int r = 0; r < 2; r++)
#pragma unroll
            for (int h = 0; h < 2; h++) {
                const float* a4 = (const float*)&av[r][h];
                const float* b4 = (const float*)&bv[r][h];
#pragma unroll
                for (int j = 0; j < 4; j++) {
                    As[buf][kc + h * 4 + j][rowA + r * 64] = f2tf(a4[j]);
                    Bs[buf][kc + h * 4 + j][rowA + r * 64] = f2tf(b4[j]);
                }
            }
    };

    ldtile(0);
    sttile(0);
    __syncthreads();

    const int NT = KDIM / 16;
#pragma unroll 1
    for (int kt = 0; kt < NT; kt++) {
        const int buf = kt & 1;
        if (kt + 1 < NT) ldtile(kt + 1);

#pragma unroll
        for (int kk = 0; kk < 16; kk += 8) {
            unsigned af[4][4], bf[8][2];
#pragma unroll
            for (int mi = 0; mi < 4; mi++) {
                af[mi][0] = As[buf][kk + t    ][wr + mi * 16 + g    ];
                af[mi][1] = As[buf][kk + t    ][wr + mi * 16 + g + 8];
                af[mi][2] = As[buf][kk + t + 4][wr + mi * 16 + g    ];
                af[mi][3] = As[buf][kk + t + 4][wr + mi * 16 + g + 8];
            }
#pragma unroll
            for (int ni = 0; ni < 8; ni++) {
                bf[ni][0] = Bs[buf][kk + t    ][wc + ni * 8 + g];
                bf[ni][1] = Bs[buf][kk + t + 4][wc + ni * 8 + g];
            }
#pragma unroll
            for (int mi = 0; mi < 4; mi++)
#pragma unroll
                for (int ni = 0; ni < 8; ni++)
                    mma_tf32(acc[mi][ni], af[mi], bf[ni]);
        }

        if (kt + 1 < NT) sttile(buf ^ 1);
        __syncthreads();
    }

#pragma unroll
    for (int mi = 0; mi < 4; mi++) {
#pragma unroll
        for (int ni = 0; ni < 8; ni++) {
            const int row = m0 + wr + mi * 16 + g;
            const int col = n0 + wc + ni * 8 + t * 2;
            float b0 = 0.f, b1 = 0.f;
            if (bias) { b0 = bias[col]; b1 = bias[col + 1]; }
            *(float2*)&C[(size_t)row * ldc + col] =
                make_float2(acc[mi][ni][0] * alpha + b0, acc[mi][ni][1] * alpha + b1);
            *(float2*)&C[(size_t)(row + 8) * ldc + col] =
                make_float2(acc[mi][ni][2] * alpha + b0, acc[mi][ni][3] * alpha + b1);
        }
    }
}

// C[8192,1024] = A[8192,1024] @ W[1024,1024]^T (+bias)
__global__ __launch_bounds__(128, 2) void proj_tf32(
    const float* __restrict__ A, const float* __restrict__ B,
    float* __restrict__ C, const float* __restrict__ bias)
{
    gemm_nt_body<EMB>(A, EMB, B, EMB, C, EMB, 1.0f, bias);
}

// att[z,q,k] = 0.125 * Q[n,q,h,:] . K[n,k,h,:]  (z = n*16+h), K-dim = 64
__global__ __launch_bounds__(128, 2) void energy_tf32(float* __restrict__ att)
{
    const int z = blockIdx.z;
    const int n = z >> 4, h = z & 15;
    gemm_nt_body<HD>(g_Q + (size_t)n * SEQ * EMB + h * HD, EMB,
                     g_K + (size_t)n * SEQ * EMB + h * HD, EMB,
                     att + (size_t)z * SEQ * SEQ, SEQ, 0.125f, nullptr);
}

// ---------------------------------------------------------------------------
// Row softmax over last dim (1024), in place, with mask[n,k] (-1e20 where 0).
// ---------------------------------------------------------------------------
__global__ __launch_bounds__(256) void softmax_kernel(
    float* __restrict__ att, const int* __restrict__ mask)
{
    __shared__ float sbuf[8];
    const int row = blockIdx.x;
    const int n = row >> 14;
    float* p = att + (size_t)row * SEQ;
    const int c = threadIdx.x * 4;
    const int* mrow = mask + n * SEQ;

    float4 x = *(const float4*)(p + c);
    if (mrow[c + 0] == 0) x.x = -1e20f;
    if (mrow[c + 1] == 0) x.y = -1e20f;
    if (mrow[c + 2] == 0) x.z = -1e20f;
    if (mrow[c + 3] == 0) x.w = -1e20f;

    float m = fmaxf(fmaxf(x.x, x.y), fmaxf(x.z, x.w));
#pragma unroll
    for (int o = 16; o; o >>= 1) m = fmaxf(m, __shfl_xor_sync(0xffffffffu, m, o));
    if ((threadIdx.x & 31) == 0) sbuf[threadIdx.x >> 5] = m;
    __syncthreads();
    m = sbuf[0];
#pragma unroll
    for (int i = 1; i < 8; i++) m = fmaxf(m, sbuf[i]);

    float4 e;
    e.x = __expf(x.x - m);
    e.y = __expf(x.y - m);
    e.z = __expf(x.z - m);
    e.w = __expf(x.w - m);
    float s = (e.x + e.y) + (e.z + e.w);
#pragma unroll
    for (int o = 16; o; o >>= 1) s += __shfl_xor_sync(0xffffffffu, s, o);
    __syncthreads();
    if ((threadIdx.x & 31) == 0) sbuf[threadIdx.x >> 5] = s;
    __syncthreads();
    s = 0.f;
#pragma unroll
    for (int i = 0; i < 8; i++) s += sbuf[i];

    const float inv = 1.0f / s;
    e.x *= inv; e.y *= inv; e.z *= inv; e.w *= inv;
    *(float4*)(p + c) = e;
}

// ---------------------------------------------------------------------------
// att*V (NN form): per z = n*16+h,  C[1024,64] = P[1024,1024] @ V[1024,64]
// CTA 128x64, 128 threads, warp tile 64x32, BK=16 double-buffered.
// As stride 136 (conflict-free), Bs stride 72 (conflict-free fragment LDS).
// ---------------------------------------------------------------------------
__global__ __launch_bounds__(128, 2) void attv_tf32(const float* __restrict__ att)
{
    const int z = blockIdx.z;
    const int n = z >> 4, h = z & 15;
    const float* A = att + (size_t)z * SEQ * SEQ;
    const float* B = g_V + (size_t)n * SEQ * EMB + h * HD;
    float* C = g_O + (size_t)n * SEQ * EMB + h * HD;

    __shared__ unsigned As[2][16][136];
    __shared__ unsigned Bs[2][16][72];

    const int tid  = threadIdx.x;
    const int m0   = blockIdx.y * 128;
    const int warp = tid >> 5;
    const int lane = tid & 31;
    const int wr   = (warp >> 1) * 64;
    const int wc   = (warp & 1) * 32;
    const int g    = lane >> 2;
    const int t    = lane & 3;

    const int rowA = tid & 63;
    const int kc   = (tid >> 6) * 8;
    const int krow = tid >> 3;          // 0..15
    const int ncol = (tid & 7) * 8;     // 0..56

    float acc[4][4][4] = {};

    const float* Ap = A + (size_t)(m0 + rowA) * SEQ + kc;
    const float* Bp = B + (size_t)krow * EMB + ncol;

    float4 av[2][2], bvv[2];

    auto ldtile = [&](int kt) {
#pragma unroll
        for (int r = 0; r < 2; r++)
#pragma unroll
            for (int h2 = 0; h2 < 2; h2++)
                av[r][h2] = *(const float4*)(Ap + (size_t)r * 64 * SEQ + kt * 16 + h2 * 4);
        bvv[0] = *(const float4*)(Bp + (size_t)kt * 16 * EMB);
        bvv[1] = *(const float4*)(Bp + (size_t)kt * 16 * EMB + 4);
    };
    auto sttile = [&](int buf) {
#pragma unroll
        for (int r = 0; r < 2; r++)
#pragma unroll
            for (int h2 = 0; h2 < 2; h2++) {
                const float* a4 = (const float*)&av[r][h2];
#pragma unroll
                for (int j = 0; j < 4; j++)
                    As[buf][kc + h2 * 4 + j][rowA + r * 64] = f2tf(a4[j]);
            }
        const float* b8 = (const float*)bvv;
#pragma unroll
        for (int j = 0; j < 8; j++)
            Bs[buf][krow][ncol + j] = f2tf(b8[j]);
    };

    ldtile(0);
    sttile(0);
    __syncthreads();

    const int NT = SEQ / 16;
#pragma unroll 1
    for (int kt = 0; kt < NT; kt++) {
        const int buf = kt & 1;
        if (kt + 1 < NT) ldtile(kt + 1);

#pragma unroll
        for (int kk = 0; kk < 16; kk += 8) {
            unsigned af[4][4], bf[4][2];
#pragma unroll
            for (int mi = 0; mi < 4; mi++) {
                af[mi][0] = As[buf][kk + t    ][wr + mi * 16 + g    ];
                af[mi][1] = As[buf][kk + t    ][wr + mi * 16 + g + 8];
                af[mi][2] = As[buf][kk + t + 4][wr + mi * 16 + g    ];
                af[mi][3] = As[buf][kk + t + 4][wr + mi * 16 + g + 8];
            }
#pragma unroll
            for (int ni = 0; ni < 4; ni++) {
                bf[ni][0] = Bs[buf][kk + t    ][wc + ni * 8 + g];
                bf[ni][1] = Bs[buf][kk + t + 4][wc + ni * 8 + g];
            }
#pragma unroll
            for (int mi = 0; mi < 4; mi++)
#pragma unroll
                for (int ni = 0; ni < 4; ni++)
                    mma_tf32(acc[mi][ni], af[mi], bf[ni]);
        }

        if (kt + 1 < NT) sttile(buf ^ 1);
        __syncthreads();
    }

#pragma unroll
    for (int mi = 0; mi < 4; mi++) {
#pragma unroll
        for (int ni = 0; ni < 4; ni++) {
            const int row = m0 + wr + mi * 16 + g;
            const int col = wc + ni * 8 + t * 2;
            *(float2*)&C[(size_t)row * EMB + col] =
                make_float2(acc[mi][ni][0], acc[mi][ni][1]);
            *(float2*)&C[(size_t)(row + 8) * EMB + col] =
                make_float2(acc[mi][ni][2], acc[mi][ni][3]);
        }
    }
}

// ---------------------------------------------------------------------------
extern "C" void kernel_launch(void* const* d_in, const int* in_sizes, int n_in,
                              void* d_out, int out_size)
{
    const float* value = (const float*)d_in[0];
    const float* key_  = (const float*)d_in[1];
    const float* query = (const float*)d_in[2];
    const int*   mask  = (const int*)d_in[3];
    const float* Wv    = (const float*)d_in[4];
    const float* Wk    = (const float*)d_in[5];
    const float* Wq    = (const float*)d_in[6];
    const float* Wo    = (const float*)d_in[7];
    const float* bo    = (const float*)d_in[8];

    float* out = (float*)d_out;                 // [8,1024,1024]
    float* att = out + OUT_ELEMS;               // [8,16,1024,1024]

    float *qp, *kp, *vp, *op;
    cudaGetSymbolAddress((void**)&qp, g_Q);
    cudaGetSymbolAddress((void**)&kp, g_K);
    cudaGetSymbolAddress((void**)&vp, g_V);
    cudaGetSymbolAddress((void**)&op, g_O);

    dim3 blk(128);
    dim3 gproj(EMB / 128, ROWS / 128);          // (8, 64)

    proj_tf32<<<gproj, blk>>>(query, Wq, qp, nullptr);
    proj_tf32<<<gproj, blk>>>(key_,  Wk, kp, nullptr);
    proj_tf32<<<gproj, blk>>>(value, Wv, vp, nullptr);

    energy_tf32<<<dim3(SEQ / 128, SEQ / 128, NB * HEADS), blk>>>(att);
    softmax_kernel<<<NB * HEADS * SEQ, 256>>>(att, mask);
    attv_tf32<<<dim3(1, SEQ / 128, NB * HEADS), blk>>>(att);

    proj_tf32<<<gproj, blk>>>(op, Wo, out, bo);
}